// round 10
// baseline (speedup 1.0000x reference)
#include <cuda_runtime.h>

// GraphNetBlock — tf32 tensor-core v5: 3-stage cp.async weight pipeline with
// ONE __syncthreads per chunk (was 2), fragment-interleaved weights,
// k-permuted A/H operand layout.
// cvt_weights + probe_idx + zero_agg -> edge_kernel -> node_kernel
// out layout: node_out [N,128] then edge_out [E,128].

#define THREADS 256
#define TILE_M 64

#define P_A  392   // As pitch (K=384), == 8 mod 32: LDS.64 frag conflict-free
#define P_AN 264   // node As pitch (K=256)
#define P_H  264   // H / O pitch
#define BUFSTRIDE 4096   // weight chunk buffer (16*256 floats max)

__device__ float g_agg[65536 * 128];
__device__ int g_is64;

// preconverted tf32 weights, fragment-interleaved
#define OFF_We1 0
#define OFF_We2 98304
#define OFF_Wer 131072
#define OFF_Wn1 180224
#define OFF_Wn2 245760
#define OFF_Wnr 278528
#define W_TOTAL 311296
__device__ float g_wtf[W_TOTAL];

#define EDGE_SMEM_F (64 * P_A + 64 * P_H + 3 * BUFSTRIDE)   // 54272 fl = 217KB
#define NODE_SMEM_F (64 * P_AN + 64 * P_H + 3 * BUFSTRIDE)  // 46080 fl = 184KB

// ---------------- helpers ----------------
__device__ __forceinline__ unsigned f2tf(float x) {
    unsigned u;
    asm("cvt.rna.tf32.f32 %0, %1;" : "=r"(u) : "f"(x));
    return u;
}
__device__ __forceinline__ float f2tf_f(float x) { return __uint_as_float(f2tf(x)); }

__device__ __forceinline__ void cpa16(float* dst, const float* src) {
    unsigned d = (unsigned)__cvta_generic_to_shared(dst);
    asm volatile("cp.async.cg.shared.global [%0], [%1], 16;" :: "r"(d), "l"(src));
}
__device__ __forceinline__ void cpa_commit() { asm volatile("cp.async.commit_group;"); }
__device__ __forceinline__ void cpa_wait1() { asm volatile("cp.async.wait_group 1;"); }
__device__ __forceinline__ void cpa_wait0() { asm volatile("cp.async.wait_group 0;"); }

__device__ __forceinline__ void mma8(float c[4], const unsigned a[4], unsigned b0, unsigned b1) {
    asm volatile(
        "mma.sync.aligned.m16n8k8.row.col.f32.tf32.tf32.f32 "
        "{%0,%1,%2,%3}, {%4,%5,%6,%7}, {%8,%9}, {%0,%1,%2,%3};"
        : "+f"(c[0]), "+f"(c[1]), "+f"(c[2]), "+f"(c[3])
        : "r"(a[0]), "r"(a[1]), "r"(a[2]), "r"(a[3]), "r"(b0), "r"(b1));
}

// load A fragment (m16k8) from k-permuted smem layout: 2 x LDS.64
// rowg must already include the lane group (m-tile row + g).
__device__ __forceinline__ void load_afrag(unsigned a[4], const float* Ap, int rowg,
                                           int pa, int kk, int t) {
    const float* p = Ap + (size_t)rowg * pa + kk + t * 2;
    float2 lo = *(const float2*)p;
    float2 hi = *(const float2*)(p + 8 * pa);
    a[0] = __float_as_uint(lo.x);
    a[2] = __float_as_uint(lo.y);
    a[1] = __float_as_uint(hi.x);
    a[3] = __float_as_uint(hi.y);
}

// copy one contiguous 16-k-row weight chunk gmem -> smem via cp.async
template<int COLS>
__device__ __forceinline__ void copy_chunk(float* BsBuf, const float* W, int kt, int tid) {
    const int NF4 = 16 * COLS / 4;
    const float* src = W + (size_t)kt * 16 * COLS;
    #pragma unroll
    for (int i = tid; i < NF4; i += THREADS) cpa16(BsBuf + i * 4, src + i * 4);
}

__device__ __forceinline__ long long load_idx(const void* ei, long long i, int is64) {
    if (is64) return ((const long long*)ei)[i];
    return (long long)((const int*)ei)[i];
}
__device__ __forceinline__ long long clamp_idx(long long v, int Nn) {
    if (v < 0) return 0;
    if (v >= Nn) return Nn - 1;
    return v;
}

__global__ void probe_idx_kernel(const void* ei, int E, int Nn) {
    int n = E < 64 ? E : 64;
    int bad = 0;
    if (threadIdx.x < n) {
        long long v = ((const long long*)ei)[threadIdx.x];
        bad = (v < 0 || v >= Nn);
    }
    unsigned anybad = __ballot_sync(0xffffffffu, bad);
    __shared__ unsigned s[2];
    if ((threadIdx.x & 31) == 0) s[threadIdx.x >> 5] = anybad;
    __syncthreads();
    if (threadIdx.x == 0) g_is64 = (s[0] | s[1]) ? 0 : 1;
}

__global__ void zero_agg_kernel(int nf4) {
    int i = blockIdx.x * blockDim.x + threadIdx.x;
    if (i < nf4) ((float4*)g_agg)[i] = make_float4(0.f, 0.f, 0.f, 0.f);
}

// convert weights to tf32 in fragment-interleaved layout
__global__ void cvt_weights_kernel(const float* We1, const float* We2, const float* Wer,
                                   const float* Wn1, const float* Wn2, const float* Wnr) {
    int f = blockIdx.x * blockDim.x + threadIdx.x;
    if (f >= W_TOTAL / 4) return;
    int i = f * 4;
    const float* src; int off; int N;
    if      (i < OFF_We2) { src = We1; off = OFF_We1; N = 256; }
    else if (i < OFF_Wn1) { src = (i < OFF_Wer) ? We2 : Wer; off = (i < OFF_Wer) ? OFF_We2 : OFF_Wer; N = 128; }
    else if (i < OFF_Wn2) { src = Wn1; off = OFF_Wn1; N = 256; }
    else if (i < OFF_Wnr) { src = Wn2; off = OFF_Wn2; N = 128; }
    else                  { src = Wnr; off = OFF_Wnr; N = 128; }
    int lf = (i - off) / 4;
    int NB = N / 16;
    int K0 = lf / (NB * 32);
    int rem = lf - K0 * NB * 32;
    int N0p = rem >> 5;
    int lane = rem & 31;
    int g = lane >> 2, t = lane & 3;
    int r0 = K0 * 8 + t, r1 = r0 + 4;
    int c0 = N0p * 16 + g, c1 = c0 + 8;
    float4 o;
    o.x = f2tf_f(src[(size_t)r0 * N + c0]);
    o.y = f2tf_f(src[(size_t)r1 * N + c0]);
    o.z = f2tf_f(src[(size_t)r0 * N + c1]);
    o.w = f2tf_f(src[(size_t)r1 * N + c1]);
    *(float4*)(g_wtf + i) = o;
}

// ---------------------------------------------------------------------------
// Edge kernel
// ---------------------------------------------------------------------------
__global__ void __launch_bounds__(THREADS, 1)
edge_kernel(const float* __restrict__ x, const float* __restrict__ ea,
            const void* __restrict__ ei,
            const float* __restrict__ be1, const float* __restrict__ be2,
            const float* __restrict__ ber,
            const float* __restrict__ ge,  const float* __restrict__ bge,
            float* __restrict__ edge_out, int E, int Nn)
{
    extern __shared__ float smem[];
    float* As = smem;                  // [64][P_A]  tf32 EH, k-permuted
    float* Hs = As + 64 * P_A;         // [64][P_H]  tf32 H1 (k-permuted), later fp32 O (plain)
    float* Bs = Hs + 64 * P_H;         // [3][BUFSTRIDE] frag-layout weight chunks

    const float* We1 = g_wtf + OFF_We1;
    const float* We2 = g_wtf + OFF_We2;
    const float* Wer = g_wtf + OFF_Wer;

    const int tid  = threadIdx.x;
    const int warp = tid >> 5;
    const int lane = tid & 31;
    const int g    = lane >> 2;
    const int t    = lane & 3;
    const int e0   = blockIdx.x * TILE_M;
    const int is64 = g_is64;

    // k-perm epilogue offsets for cols 2t, 2t+1 within an 8-col block
    const int d0 = (((2 * t) & 3) << 1) | ((2 * t) >> 2);
    const int d1 = (((2 * t + 1) & 3) << 1) | ((2 * t + 1) >> 2);

    // ---- gather EH = [ea | x[src] | x[dst]] into As (tf32, k-permuted) ----
    #pragma unroll
    for (int sweep = 0; sweep < 8; ++sweep) {
        int m = sweep * 8 + warp;
        int ecl = min(e0 + m, E - 1);
        long long s = clamp_idx(load_idx(ei, ecl, is64), Nn);
        long long d = clamp_idx(load_idx(ei, (long long)E + ecl, is64), Nn);
        int k = lane * 4;
        int off = (k & ~7) + ((k >> 2) & 1);
        float4 v0 = *(const float4*)(ea + (size_t)ecl * 128 + k);
        float4 v1 = *(const float4*)(x  + (size_t)s   * 128 + k);
        float4 v2 = *(const float4*)(x  + (size_t)d   * 128 + k);
        float* row = As + (size_t)m * P_A;
        row[off + 0] = f2tf_f(v0.x); row[off + 2] = f2tf_f(v0.y);
        row[off + 4] = f2tf_f(v0.z); row[off + 6] = f2tf_f(v0.w);
        row[128 + off + 0] = f2tf_f(v1.x); row[128 + off + 2] = f2tf_f(v1.y);
        row[128 + off + 4] = f2tf_f(v1.z); row[128 + off + 6] = f2tf_f(v1.w);
        row[256 + off + 0] = f2tf_f(v2.x); row[256 + off + 2] = f2tf_f(v2.y);
        row[256 + off + 4] = f2tf_f(v2.z); row[256 + off + 6] = f2tf_f(v2.w);
    }
    // note: sync before first compute is provided by the pipeline's first
    // iteration barrier below; but the first cp.async copies overlap gather.

    const int mw = warp & 1;         // 2 x m32
    const int nw = warp >> 1;        // 4 x n64 (GEMM1) / 4 x n32 (GEMM2)
    const int mb = mw * 32;

    // ================= GEMM1: H = EH @ We1  (64x256, K=384) =================
    {
        float acc[2][8][4];
        #pragma unroll
        for (int mi = 0; mi < 2; ++mi)
            #pragma unroll
            for (int ni = 0; ni < 8; ++ni)
                #pragma unroll
                for (int q = 0; q < 4; ++q) acc[mi][ni][q] = 0.f;

        copy_chunk<256>(Bs,             We1, 0, tid); cpa_commit();
        copy_chunk<256>(Bs + BUFSTRIDE, We1, 1, tid); cpa_commit();
        int buf2 = 2;   // next buffer slot to fill (rotates 2,0,1,2,...)
        int bufc = 0;   // buffer holding current chunk
        for (int kt = 0; kt < 24; ++kt) {
            if (kt + 1 < 24) cpa_wait1(); else cpa_wait0();
            __syncthreads();
            if (kt + 2 < 24) {
                copy_chunk<256>(Bs + buf2 * BUFSTRIDE, We1, kt + 2, tid);
                cpa_commit();
            }
            const unsigned* B = (const unsigned*)(Bs + bufc * BUFSTRIDE);
            buf2 = bufc;
            bufc = (bufc == 2) ? 0 : bufc + 1;
            #pragma unroll
            for (int ks = 0; ks < 2; ++ks) {
                int kk = kt * 16 + ks * 8;
                unsigned a[2][4];
                load_afrag(a[0], As, mb + g, P_A, kk, t);
                load_afrag(a[1], As, mb + 16 + g, P_A, kk, t);
                #pragma unroll
                for (int j = 0; j < 4; ++j) {
                    uint4 bf = *(const uint4*)(B + (((ks * 16) + nw * 4 + j) * 32 + lane) * 4);
                    mma8(acc[0][2 * j],     a[0], bf.x, bf.y);
                    mma8(acc[1][2 * j],     a[1], bf.x, bf.y);
                    mma8(acc[0][2 * j + 1], a[0], bf.z, bf.w);
                    mma8(acc[1][2 * j + 1], a[1], bf.z, bf.w);
                }
            }
        }
        __syncthreads();   // all reads of last chunk done before GEMM2 refills

        // SiLU + bias -> Hs (tf32, k-permuted cols)
        const int nb = nw * 64;
        #pragma unroll
        for (int mi = 0; mi < 2; ++mi) {
            int r0 = mb + mi * 16 + g;
            #pragma unroll
            for (int ni = 0; ni < 8; ++ni) {
                int col8 = nb + ni * 8;
                float b0 = __ldg(&be1[col8 + 2 * t]), b1 = __ldg(&be1[col8 + 2 * t + 1]);
                float v;
                v = acc[mi][ni][0] + b0; Hs[(size_t)r0 * P_H + col8 + d0]        = f2tf_f(v / (1.f + __expf(-v)));
                v = acc[mi][ni][1] + b1; Hs[(size_t)r0 * P_H + col8 + d1]        = f2tf_f(v / (1.f + __expf(-v)));
                v = acc[mi][ni][2] + b0; Hs[(size_t)(r0 + 8) * P_H + col8 + d0]  = f2tf_f(v / (1.f + __expf(-v)));
                v = acc[mi][ni][3] + b1; Hs[(size_t)(r0 + 8) * P_H + col8 + d1]  = f2tf_f(v / (1.f + __expf(-v)));
            }
        }
        __syncthreads();
    }

    // ============ GEMM2: O = H @ We2 + EH @ Wer  (64x128) ============
    float acc2[2][4][4];
    #pragma unroll
    for (int mi = 0; mi < 2; ++mi)
        #pragma unroll
        for (int ni = 0; ni < 4; ++ni)
            #pragma unroll
            for (int q = 0; q < 4; ++q) acc2[mi][ni][q] = 0.f;
    {
        const int NC = 40;    // 16 chunks (We2 over H) + 24 chunks (Wer over EH)
        copy_chunk<128>(Bs,             We2, 0, tid); cpa_commit();
        copy_chunk<128>(Bs + BUFSTRIDE, We2, 1, tid); cpa_commit();
        int buf2 = 2;
        int bufc = 0;
        for (int c = 0; c < NC; ++c) {
            if (c + 1 < NC) cpa_wait1(); else cpa_wait0();
            __syncthreads();
            if (c + 2 < NC) {
                const float* Wn = (c + 2 < 16) ? We2 : Wer;
                int ktn = (c + 2 < 16) ? (c + 2) : (c + 2 - 16);
                copy_chunk<128>(Bs + buf2 * BUFSTRIDE, Wn, ktn, tid);
                cpa_commit();
            }
            const unsigned* B = (const unsigned*)(Bs + bufc * BUFSTRIDE);
            buf2 = bufc;
            bufc = (bufc == 2) ? 0 : bufc + 1;
            const float* Ap = (c < 16) ? Hs : As;
            const int pa    = (c < 16) ? P_H : P_A;
            const int kk0   = (c < 16) ? c * 16 : (c - 16) * 16;
            #pragma unroll
            for (int ks = 0; ks < 2; ++ks) {
                int kk = kk0 + ks * 8;
                unsigned a[2][4];
                load_afrag(a[0], Ap, mb + g, pa, kk, t);
                load_afrag(a[1], Ap, mb + 16 + g, pa, kk, t);
                #pragma unroll
                for (int j = 0; j < 2; ++j) {
                    uint4 bf = *(const uint4*)(B + (((ks * 8) + nw * 2 + j) * 32 + lane) * 4);
                    mma8(acc2[0][2 * j],     a[0], bf.x, bf.y);
                    mma8(acc2[1][2 * j],     a[1], bf.x, bf.y);
                    mma8(acc2[0][2 * j + 1], a[0], bf.z, bf.w);
                    mma8(acc2[1][2 * j + 1], a[1], bf.z, bf.w);
                }
            }
        }
        __syncthreads();   // all reads of Hs (H) done before overwriting with O
    }

    // store O (fp32, plain cols) into Hs
    {
        const int nb = nw * 32;
        #pragma unroll
        for (int mi = 0; mi < 2; ++mi) {
            int r0 = mb + mi * 16 + g;
            #pragma unroll
            for (int ni = 0; ni < 4; ++ni) {
                int c0 = nb + ni * 8 + 2 * t;
                Hs[(size_t)r0 * P_H + c0]           = acc2[mi][ni][0];
                Hs[(size_t)r0 * P_H + c0 + 1]       = acc2[mi][ni][1];
                Hs[(size_t)(r0 + 8) * P_H + c0]     = acc2[mi][ni][2];
                Hs[(size_t)(r0 + 8) * P_H + c0 + 1] = acc2[mi][ni][3];
            }
        }
    }
    __syncthreads();

    // ---- epilogue: bias + LayerNorm + write + scatter ----
    int c4 = lane * 4;
    float4 g4 = *(const float4*)&ge[c4];
    float4 q4 = *(const float4*)&bge[c4];
    float bo0 = be2[c4 + 0] + ber[c4 + 0];
    float bo1 = be2[c4 + 1] + ber[c4 + 1];
    float bo2 = be2[c4 + 2] + ber[c4 + 2];
    float bo3 = be2[c4 + 3] + ber[c4 + 3];

    #pragma unroll
    for (int i = 0; i < 8; ++i) {
        int m = warp * 8 + i;
        const float* row = Hs + (size_t)m * P_H;
        float v0 = row[c4 + 0] + bo0, v1 = row[c4 + 1] + bo1;
        float v2 = row[c4 + 2] + bo2, v3 = row[c4 + 3] + bo3;
        float s = v0 + v1 + v2 + v3;
        float sq = v0 * v0 + v1 * v1 + v2 * v2 + v3 * v3;
        #pragma unroll
        for (int o = 16; o > 0; o >>= 1) {
            s  += __shfl_xor_sync(0xffffffffu, s, o);
            sq += __shfl_xor_sync(0xffffffffu, sq, o);
        }
        float mu  = s * (1.f / 128.f);
        float var = sq * (1.f / 128.f) - mu * mu;
        float rstd = rsqrtf(var + 1e-5f);
        int e = e0 + m;
        if (e < E) {
            float4 y;
            y.x = (v0 - mu) * rstd * g4.x + q4.x;
            y.y = (v1 - mu) * rstd * g4.y + q4.y;
            y.z = (v2 - mu) * rstd * g4.z + q4.z;
            y.w = (v3 - mu) * rstd * g4.w + q4.w;
            *(float4*)&edge_out[(size_t)e * 128 + c4] = y;
            long long d = clamp_idx(load_idx(ei, (long long)E + e, is64), Nn);
            float* ap = g_agg + (size_t)d * 128 + c4;
            atomicAdd(ap + 0, y.x);
            atomicAdd(ap + 1, y.y);
            atomicAdd(ap + 2, y.z);
            atomicAdd(ap + 3, y.w);
        }
    }
}

// ---------------------------------------------------------------------------
// Node kernel
// ---------------------------------------------------------------------------
__global__ void __launch_bounds__(THREADS, 1)
node_kernel(const float* __restrict__ x,
            const float* __restrict__ bn1, const float* __restrict__ bn2,
            const float* __restrict__ bnr,
            const float* __restrict__ gn,  const float* __restrict__ bgn,
            float* __restrict__ node_out, int Nn)
{
    extern __shared__ float smem[];
    float* As = smem;                   // [64][P_AN] k-permuted
    float* Hs = As + 64 * P_AN;         // [64][P_H]
    float* Bs = Hs + 64 * P_H;          // [3][BUFSTRIDE]

    const float* Wn1 = g_wtf + OFF_Wn1;
    const float* Wn2 = g_wtf + OFF_Wn2;
    const float* Wnr = g_wtf + OFF_Wnr;

    const int tid  = threadIdx.x;
    const int warp = tid >> 5;
    const int lane = tid & 31;
    const int g    = lane >> 2;
    const int t    = lane & 3;
    const int n0   = blockIdx.x * TILE_M;

    const int d0 = (((2 * t) & 3) << 1) | ((2 * t) >> 2);
    const int d1 = (((2 * t + 1) & 3) << 1) | ((2 * t + 1) >> 2);

    #pragma unroll
    for (int sweep = 0; sweep < 8; ++sweep) {
        int m = sweep * 8 + warp;
        int nn = min(n0 + m, Nn - 1);
        int k = lane * 4;
        int off = (k & ~7) + ((k >> 2) & 1);
        float4 v0 = *(const float4*)(x     + (size_t)nn * 128 + k);
        float4 v1 = *(const float4*)(g_agg + (size_t)nn * 128 + k);
        float* row = As + (size_t)m * P_AN;
        row[off + 0] = f2tf_f(v0.x); row[off + 2] = f2tf_f(v0.y);
        row[off + 4] = f2tf_f(v0.z); row[off + 6] = f2tf_f(v0.w);
        row[128 + off + 0] = f2tf_f(v1.x); row[128 + off + 2] = f2tf_f(v1.y);
        row[128 + off + 4] = f2tf_f(v1.z); row[128 + off + 6] = f2tf_f(v1.w);
    }

    const int mw = warp & 1;
    const int nw = warp >> 1;
    const int mb = mw * 32;

    // GEMM1: H = NH @ Wn1 (64x256, K=256)
    {
        float acc[2][8][4];
        #pragma unroll
        for (int mi = 0; mi < 2; ++mi)
            #pragma unroll
            for (int ni = 0; ni < 8; ++ni)
                #pragma unroll
                for (int q = 0; q < 4; ++q) acc[mi][ni][q] = 0.f;

        copy_chunk<256>(Bs,             Wn1, 0, tid); cpa_commit();
        copy_chunk<256>(Bs + BUFSTRIDE, Wn1, 1, tid); cpa_commit();
        int buf2 = 2;
        int bufc = 0;
        for (int kt = 0; kt < 16; ++kt) {
            if (kt + 1 < 16) cpa_wait1(); else cpa_wait0();
            __syncthreads();
            if (kt + 2 < 16) {
                copy_chunk<256>(Bs + buf2 * BUFSTRIDE, Wn1, kt + 2, tid);
                cpa_commit();
            }
            const unsigned* B = (const unsigned*)(Bs + bufc * BUFSTRIDE);
            buf2 = bufc;
            bufc = (bufc == 2) ? 0 : bufc + 1;
            #pragma unroll
            for (int ks = 0; ks < 2; ++ks) {
                int kk = kt * 16 + ks * 8;
                unsigned a[2][4];
                load_afrag(a[0], As, mb + g, P_AN, kk, t);
                load_afrag(a[1], As, mb + 16 + g, P_AN, kk, t);
                #pragma unroll
                for (int j = 0; j < 4; ++j) {
                    uint4 bf = *(const uint4*)(B + (((ks * 16) + nw * 4 + j) * 32 + lane) * 4);
                    mma8(acc[0][2 * j],     a[0], bf.x, bf.y);
                    mma8(acc[1][2 * j],     a[1], bf.x, bf.y);
                    mma8(acc[0][2 * j + 1], a[0], bf.z, bf.w);
                    mma8(acc[1][2 * j + 1], a[1], bf.z, bf.w);
                }
            }
        }
        __syncthreads();

        const int nb = nw * 64;
        #pragma unroll
        for (int mi = 0; mi < 2; ++mi) {
            int r0 = mb + mi * 16 + g;
            #pragma unroll
            for (int ni = 0; ni < 8; ++ni) {
                int col8 = nb + ni * 8;
                float b0 = __ldg(&bn1[col8 + 2 * t]), b1 = __ldg(&bn1[col8 + 2 * t + 1]);
                float v;
                v = acc[mi][ni][0] + b0; Hs[(size_t)r0 * P_H + col8 + d0]        = f2tf_f(v / (1.f + __expf(-v)));
                v = acc[mi][ni][1] + b1; Hs[(size_t)r0 * P_H + col8 + d1]        = f2tf_f(v / (1.f + __expf(-v)));
                v = acc[mi][ni][2] + b0; Hs[(size_t)(r0 + 8) * P_H + col8 + d0]  = f2tf_f(v / (1.f + __expf(-v)));
                v = acc[mi][ni][3] + b1; Hs[(size_t)(r0 + 8) * P_H + col8 + d1]  = f2tf_f(v / (1.f + __expf(-v)));
            }
        }
        __syncthreads();
    }

    // GEMM2: O = H @ Wn2 + NH @ Wnr (64x128, K=256 each)
    float acc2[2][4][4];
    #pragma unroll
    for (int mi = 0; mi < 2; ++mi)
        #pragma unroll
        for (int ni = 0; ni < 4; ++ni)
            #pragma unroll
            for (int q = 0; q < 4; ++q) acc2[mi][ni][q] = 0.f;
    {
        const int NC = 32;   // 16 (Wn2 over H) + 16 (Wnr over NH)
        copy_chunk<128>(Bs,             Wn2, 0, tid); cpa_commit();
        copy_chunk<128>(Bs + BUFSTRIDE, Wn2, 1, tid); cpa_commit();
        int buf2 = 2;
        int bufc = 0;
        for (int c = 0; c < NC; ++c) {
            if (c + 1 < NC) cpa_wait1(); else cpa_wait0();
            __syncthreads();
            if (c + 2 < NC) {
                const float* Wnx = (c + 2 < 16) ? Wn2 : Wnr;
                int ktn = (c + 2 < 16) ? (c + 2) : (c + 2 - 16);
                copy_chunk<128>(Bs + buf2 * BUFSTRIDE, Wnx, ktn, tid);
                cpa_commit();
            }
            const unsigned* B = (const unsigned*)(Bs + bufc * BUFSTRIDE);
            buf2 = bufc;
            bufc = (bufc == 2) ? 0 : bufc + 1;
            const float* Ap = (c < 16) ? Hs : As;
            const int pa    = (c < 16) ? P_H : P_AN;
            const int kk0   = (c < 16) ? c * 16 : (c - 16) * 16;
            #pragma unroll
            for (int ks = 0; ks < 2; ++ks) {
                int kk = kk0 + ks * 8;
                unsigned a[2][4];
                load_afrag(a[0], Ap, mb + g, pa, kk, t);
                load_afrag(a[1], Ap, mb + 16 + g, pa, kk, t);
                #pragma unroll
                for (int j = 0; j < 2; ++j) {
                    uint4 bf = *(const uint4*)(B + (((ks * 8) + nw * 2 + j) * 32 + lane) * 4);
                    mma8(acc2[0][2 * j],     a[0], bf.x, bf.y);
                    mma8(acc2[1][2 * j],     a[1], bf.x, bf.y);
                    mma8(acc2[0][2 * j + 1], a[0], bf.z, bf.w);
                    mma8(acc2[1][2 * j + 1], a[1], bf.z, bf.w);
                }
            }
        }
        __syncthreads();
    }

    {
        const int nb = nw * 32;
        #pragma unroll
        for (int mi = 0; mi < 2; ++mi) {
            int r0 = mb + mi * 16 + g;
            #pragma unroll
            for (int ni = 0; ni < 4; ++ni) {
                int c0 = nb + ni * 8 + 2 * t;
                Hs[(size_t)r0 * P_H + c0]           = acc2[mi][ni][0];
                Hs[(size_t)r0 * P_H + c0 + 1]       = acc2[mi][ni][1];
                Hs[(size_t)(r0 + 8) * P_H + c0]     = acc2[mi][ni][2];
                Hs[(size_t)(r0 + 8) * P_H + c0 + 1] = acc2[mi][ni][3];
            }
        }
    }
    __syncthreads();

    int c4 = lane * 4;
    float4 g4 = *(const float4*)&gn[c4];
    float4 q4 = *(const float4*)&bgn[c4];
    float bo0 = bn2[c4 + 0] + bnr[c4 + 0];
    float bo1 = bn2[c4 + 1] + bnr[c4 + 1];
    float bo2 = bn2[c4 + 2] + bnr[c4 + 2];
    float bo3 = bn2[c4 + 3] + bnr[c4 + 3];

    #pragma unroll
    for (int i = 0; i < 8; ++i) {
        int m = warp * 8 + i;
        const float* row = Hs + (size_t)m * P_H;
        float v0 = row[c4 + 0] + bo0, v1 = row[c4 + 1] + bo1;
        float v2 = row[c4 + 2] + bo2, v3 = row[c4 + 3] + bo3;
        float s = v0 + v1 + v2 + v3;
        float sq = v0 * v0 + v1 * v1 + v2 * v2 + v3 * v3;
        #pragma unroll
        for (int o = 16; o > 0; o >>= 1) {
            s  += __shfl_xor_sync(0xffffffffu, s, o);
            sq += __shfl_xor_sync(0xffffffffu, sq, o);
        }
        float mu  = s * (1.f / 128.f);
        float var = sq * (1.f / 128.f) - mu * mu;
        float rstd = rsqrtf(var + 1e-5f);
        int n = n0 + m;
        if (n < Nn) {
            float4 y;
            y.x = (v0 - mu) * rstd * g4.x + q4.x;
            y.y = (v1 - mu) * rstd * g4.y + q4.y;
            y.z = (v2 - mu) * rstd * g4.z + q4.z;
            y.w = (v3 - mu) * rstd * g4.w + q4.w;
            *(float4*)&node_out[(size_t)n * 128 + c4] = y;
        }
    }
}

extern "C" void kernel_launch(void* const* d_in, const int* in_sizes, int n_in,
                              void* d_out, int out_size) {
    const float* x   = (const float*)d_in[0];
    const float* ea  = (const float*)d_in[1];
    const void*  ei  = d_in[2];
    const float* We1 = (const float*)d_in[3];
    const float* be1 = (const float*)d_in[4];
    const float* We2 = (const float*)d_in[5];
    const float* be2 = (const float*)d_in[6];
    const float* Wer = (const float*)d_in[7];
    const float* ber = (const float*)d_in[8];
    const float* ge  = (const float*)d_in[9];
    const float* bge = (const float*)d_in[10];
    const float* Wn1 = (const float*)d_in[11];
    const float* bn1 = (const float*)d_in[12];
    const float* Wn2 = (const float*)d_in[13];
    const float* bn2 = (const float*)d_in[14];
    const float* Wnr = (const float*)d_in[15];
    const float* bnr = (const float*)d_in[16];
    const float* gn  = (const float*)d_in[17];
    const float* bgn = (const float*)d_in[18];

    int Nn = in_sizes[0] / 128;
    int E  = in_sizes[1] / 128;

    float* out      = (float*)d_out;
    float* node_out = out;
    float* edge_out = out + (size_t)Nn * 128;

    cudaFuncSetAttribute(edge_kernel, cudaFuncAttributeMaxDynamicSharedMemorySize,
                         EDGE_SMEM_F * 4);
    cudaFuncSetAttribute(node_kernel, cudaFuncAttributeMaxDynamicSharedMemorySize,
                         NODE_SMEM_F * 4);

    probe_idx_kernel<<<1, 64>>>(ei, E, Nn);
    cvt_weights_kernel<<<(W_TOTAL / 4 + 255) / 256, 256>>>(We1, We2, Wer, Wn1, Wn2, Wnr);

    int nf4 = Nn * 32;
    zero_agg_kernel<<<(nf4 + 255) / 256, 256>>>(nf4);

    edge_kernel<<<(E + TILE_M - 1) / TILE_M, THREADS, EDGE_SMEM_F * 4>>>(
        x, ea, ei, be1, be2, ber, ge, bge, edge_out, E, Nn);

    node_kernel<<<(Nn + TILE_M - 1) / TILE_M, THREADS, NODE_SMEM_F * 4>>>(
        x, bn1, bn2, bnr, gn, bgn, node_out, Nn);
}

// round 16
// speedup vs baseline: 2.3493x; 2.3493x over previous
#include <cuda_runtime.h>
#include <cuda_fp16.h>

// GraphNetBlock — fp16 mma.sync.m16n8k16 (sm_103 base ISA; tcgen05 unavailable
// because harness PTX targets sm_103, not sm_103a).
// Halved smem bytes/MAC vs tf32 + 2 CTAs/SM.
// cvt_weights + probe + zero_agg -> edge_kernel -> node_kernel
// out layout: node_out [N,128] then edge_out [E,128].

#define THREADS 256
#define TILE_M 64

#define P_A  400   // A pitch in halves (K=384+pad); 200 words == 8 mod 32
#define P_AN 272   // node A pitch (K=256+pad); 136 words == 8 mod 32
#define P_H  272   // H pitch (halves)
#define P_O  132   // O pitch (floats)

// smem maps (bytes)
#define E_A 0
#define E_H 51200            // 64*400*2
#define E_B 86016            // E_H + 64*272*2
#define E_TOTAL 102400       // E_B + 2*8192
#define N_A 0
#define N_H 34816            // 64*272*2
#define N_B 69632
#define N_TOTAL 86016
#define BUFB 8192            // weight chunk buffer stride (bytes)

__device__ float g_agg[65536 * 128];
__device__ int g_is64;

// f16 weights, fragment-interleaved for m16n8k16 (16-k chunks)
#define OFF_We1 0
#define OFF_We2 98304
#define OFF_Wer 131072
#define OFF_Wn1 180224
#define OFF_Wn2 245760
#define OFF_Wnr 278528
#define W_TOTAL 311296
__device__ __half g_wtf[W_TOTAL];

// ---------------- helpers ----------------
__device__ __forceinline__ void mma16(float c[4], const unsigned a[4], unsigned b0, unsigned b1) {
    asm volatile(
        "mma.sync.aligned.m16n8k16.row.col.f32.f16.f16.f32 "
        "{%0,%1,%2,%3}, {%4,%5,%6,%7}, {%8,%9}, {%0,%1,%2,%3};"
        : "+f"(c[0]), "+f"(c[1]), "+f"(c[2]), "+f"(c[3])
        : "r"(a[0]), "r"(a[1]), "r"(a[2]), "r"(a[3]), "r"(b0), "r"(b1));
}

// A fragment (m16k16) from k-permuted f16 tile: 2 x LDS.64
// rowg includes lane group g. kk = chunk*16.
__device__ __forceinline__ void load_af(unsigned a[4], const __half* Ap, int rowg,
                                        int pa, int kk, int t) {
    const __half* p = Ap + (size_t)rowg * pa + kk + t * 4;
    uint2 lo = *(const uint2*)p;
    uint2 hi = *(const uint2*)(p + 8 * pa);
    a[0] = lo.x; a[1] = hi.x; a[2] = lo.y; a[3] = hi.y;
}

// store 4 fp32 as f16 at (row, k0..k0+3) with k16-block permutation
// perm p(v) = 4*((v&7)>>1) + ((v>>3)<<1) + (v&1); pairs (even v, v+1) contiguous
__device__ __forceinline__ void st_perm4(__half* row, int k0, float4 v) {
    int kb = k0 & ~15;
    int v0 = k0 & 15;
    int p0 = ((v0 >> 1) & 3) * 4 + ((v0 >> 3) << 1);
    int v2 = v0 + 2;
    int p2 = ((v2 >> 1) & 3) * 4 + ((v2 >> 3) << 1);
    *(__half2*)(row + kb + p0) = __floats2half2_rn(v.x, v.y);
    *(__half2*)(row + kb + p2) = __floats2half2_rn(v.z, v.w);
}

__device__ __forceinline__ void cpa16(char* dst, const char* src) {
    unsigned d = (unsigned)__cvta_generic_to_shared(dst);
    asm volatile("cp.async.cg.shared.global [%0], [%1], 16;" :: "r"(d), "l"(src));
}
__device__ __forceinline__ void cpa_commit() { asm volatile("cp.async.commit_group;"); }
__device__ __forceinline__ void cpa_wait1() { asm volatile("cp.async.wait_group 1;"); }
__device__ __forceinline__ void cpa_wait0() { asm volatile("cp.async.wait_group 0;"); }

// copy one frag-layout weight chunk (NHALVES halves, contiguous) gmem -> smem
template<int NHALVES>
__device__ __forceinline__ void copy_w(char* dst, const __half* wbase, int chunk, int tid) {
    const char* src = (const char*)(wbase + (size_t)chunk * NHALVES);
    #pragma unroll
    for (int i = tid * 16; i < NHALVES * 2; i += THREADS * 16) cpa16(dst + i, src + i);
}

__device__ __forceinline__ long long ldidx(const void* ei, long long i, int is64) {
    if (is64) return ((const long long*)ei)[i];
    return (long long)((const int*)ei)[i];
}
__device__ __forceinline__ long long clampi(long long v, int Nn) {
    if (v < 0) return 0;
    if (v >= Nn) return Nn - 1;
    return v;
}

__global__ void probe_idx_kernel(const void* ei, int E, int Nn) {
    int n = E < 64 ? E : 64;
    int bad = 0;
    if (threadIdx.x < n) {
        long long v = ((const long long*)ei)[threadIdx.x];
        bad = (v < 0 || v >= Nn);
    }
    unsigned ab = __ballot_sync(0xffffffffu, bad);
    __shared__ unsigned s[2];
    if ((threadIdx.x & 31) == 0) s[threadIdx.x >> 5] = ab;
    __syncthreads();
    if (threadIdx.x == 0) g_is64 = (s[0] | s[1]) ? 0 : 1;
}

__global__ void zero_agg_kernel(int nf4) {
    int i = blockIdx.x * blockDim.x + threadIdx.x;
    if (i < nf4) ((float4*)g_agg)[i] = make_float4(0.f, 0.f, 0.f, 0.f);
}

// fp32 W[K][N] -> f16 fragment-interleaved, 16-k chunks.
// element (k,n): kt=k>>4, kk=k&15; lane=(n&7)*4 + ((kk&7)>>1); h=((kk>>3)<<1)|(kk&1);
// T=n>>3; dest = off + kt*N*16 + ((T>>1)*32+lane)*8 + (T&1)*4 + h
__global__ void cvt_weights_kernel(const float* We1, const float* We2, const float* Wer,
                                   const float* Wn1, const float* Wn2, const float* Wnr) {
    int i = blockIdx.x * blockDim.x + threadIdx.x;
    if (i >= W_TOTAL) return;
    const float* src; int off; int N;
    if      (i < OFF_We2) { src = We1; off = OFF_We1; N = 256; }
    else if (i < OFF_Wer) { src = We2; off = OFF_We2; N = 128; }
    else if (i < OFF_Wn1) { src = Wer; off = OFF_Wer; N = 128; }
    else if (i < OFF_Wn2) { src = Wn1; off = OFF_Wn1; N = 256; }
    else if (i < OFF_Wnr) { src = Wn2; off = OFF_Wn2; N = 128; }
    else                  { src = Wnr; off = OFF_Wnr; N = 128; }
    int lf = i - off;
    int k = lf / N, n = lf % N;
    int kt = k >> 4, kk = k & 15;
    int lane = (n & 7) * 4 + ((kk & 7) >> 1);
    int h = ((kk >> 3) << 1) | (kk & 1);
    int T = n >> 3;
    int dest = off + kt * N * 16 + ((T >> 1) * 32 + lane) * 8 + (T & 1) * 4 + h;
    g_wtf[dest] = __float2half_rn(src[lf]);
}

// ---------------------------------------------------------------------------
// Edge kernel: 64 edges/CTA, 2 CTAs/SM
// ---------------------------------------------------------------------------
__global__ void __launch_bounds__(THREADS, 2)
edge_kernel(const float* __restrict__ x, const float* __restrict__ ea,
            const void* __restrict__ ei,
            const float* __restrict__ be1, const float* __restrict__ be2,
            const float* __restrict__ ber,
            const float* __restrict__ ge,  const float* __restrict__ bge,
            float* __restrict__ edge_out, int E, int Nn)
{
    extern __shared__ char smem[];
    __half* Ah = (__half*)(smem + E_A);
    __half* Hh = (__half*)(smem + E_H);
    float*  O  = (float*)(smem + E_H);
    char*   Bs = smem + E_B;

    const int tid  = threadIdx.x;
    const int warp = tid >> 5;
    const int lane = tid & 31;
    const int g    = lane >> 2;
    const int t    = lane & 3;
    const int e0   = blockIdx.x * TILE_M;
    const int is64 = g_is64;

    // gather EH = [ea | x[src] | x[dst]] (f16, k-permuted)
    #pragma unroll
    for (int sweep = 0; sweep < 8; ++sweep) {
        int m = sweep * 8 + warp;
        long long ecl = min(e0 + m, E - 1);
        long long s = clampi(ldidx(ei, ecl, is64), Nn);
        long long d = clampi(ldidx(ei, (long long)E + ecl, is64), Nn);
        int k = lane * 4;
        float4 v0 = *(const float4*)(ea + ecl * 128 + k);
        float4 v1 = *(const float4*)(x + s * 128 + k);
        float4 v2 = *(const float4*)(x + d * 128 + k);
        __half* row = Ah + (size_t)m * P_A;
        st_perm4(row, k, v0);
        st_perm4(row, 128 + k, v1);
        st_perm4(row, 256 + k, v2);
    }
    __syncthreads();

    const int mw = warp & 1;         // 2 x m32
    const int nw = warp >> 1;        // 4 x n64 (GEMM1) / n32 (GEMM2)
    const int mb = mw * 32;

    // ============ GEMM1: D1 = EH @ We1^T (64x256, K=384, 24 chunks) ============
    {
        float acc[2][8][4];
        #pragma unroll
        for (int mi = 0; mi < 2; ++mi)
            #pragma unroll
            for (int ni = 0; ni < 8; ++ni)
                #pragma unroll
                for (int q = 0; q < 4; ++q) acc[mi][ni][q] = 0.f;

        copy_w<4096>(Bs, g_wtf + OFF_We1, 0, tid);
        cpa_commit();
        for (int c = 0; c < 24; ++c) {
            if (c + 1 < 24) {
                copy_w<4096>(Bs + ((c + 1) & 1) * BUFB, g_wtf + OFF_We1, c + 1, tid);
                cpa_commit();
                cpa_wait1();
            } else {
                cpa_wait0();
            }
            __syncthreads();
            const uint4* B = (const uint4*)(Bs + (c & 1) * BUFB);
            unsigned a[2][4];
            load_af(a[0], Ah, mb + g, P_A, c * 16, t);
            load_af(a[1], Ah, mb + 16 + g, P_A, c * 16, t);
            #pragma unroll
            for (int j = 0; j < 4; ++j) {
                uint4 bf = B[(nw * 4 + j) * 32 + lane];
                mma16(acc[0][2 * j],     a[0], bf.x, bf.y);
                mma16(acc[1][2 * j],     a[1], bf.x, bf.y);
                mma16(acc[0][2 * j + 1], a[0], bf.z, bf.w);
                mma16(acc[1][2 * j + 1], a[1], bf.z, bf.w);
            }
            __syncthreads();
        }

        // SiLU + bias -> H (f16, k-permuted)
        const int nb = nw * 64;
        #pragma unroll
        for (int mi = 0; mi < 2; ++mi) {
            int r0 = mb + mi * 16 + g;
            #pragma unroll
            for (int ni = 0; ni < 8; ++ni) {
                int c0 = nb + ni * 8 + 2 * t;
                float b0 = __ldg(&be1[c0]), b1 = __ldg(&be1[c0 + 1]);
                float s0 = acc[mi][ni][0] + b0, s1 = acc[mi][ni][1] + b1;
                float s2 = acc[mi][ni][2] + b0, s3 = acc[mi][ni][3] + b1;
                s0 = s0 / (1.f + __expf(-s0));
                s1 = s1 / (1.f + __expf(-s1));
                s2 = s2 / (1.f + __expf(-s2));
                s3 = s3 / (1.f + __expf(-s3));
                int base = (nb + ni * 8) & ~15;
                int pp = 4 * t + 2 * (ni & 1);
                *(__half2*)(Hh + (size_t)r0 * P_H + base + pp)       = __floats2half2_rn(s0, s1);
                *(__half2*)(Hh + (size_t)(r0 + 8) * P_H + base + pp) = __floats2half2_rn(s2, s3);
            }
        }
        __syncthreads();
    }

    // ============ GEMM2: O = H @ We2^T (16) + EH @ Wer^T (24 chunks) ============
    float acc2[2][4][4];
    #pragma unroll
    for (int mi = 0; mi < 2; ++mi)
        #pragma unroll
        for (int ni = 0; ni < 4; ++ni)
            #pragma unroll
            for (int q = 0; q < 4; ++q) acc2[mi][ni][q] = 0.f;
    {
        const int NC = 40;
        copy_w<2048>(Bs, g_wtf + OFF_We2, 0, tid);
        cpa_commit();
        for (int c = 0; c < NC; ++c) {
            if (c + 1 < NC) {
                const __half* wsrc = (c + 1 < 16) ? (g_wtf + OFF_We2) : (g_wtf + OFF_Wer);
                int cn = (c + 1 < 16) ? (c + 1) : (c + 1 - 16);
                copy_w<2048>(Bs + ((c + 1) & 1) * BUFB, wsrc, cn, tid);
                cpa_commit();
                cpa_wait1();
            } else {
                cpa_wait0();
            }
            __syncthreads();
            const uint4* B = (const uint4*)(Bs + (c & 1) * BUFB);
            const __half* Ap = (c < 16) ? Hh : Ah;
            const int pa     = (c < 16) ? P_H : P_A;
            const int kk     = ((c < 16) ? c : (c - 16)) * 16;
            unsigned a[2][4];
            load_af(a[0], Ap, mb + g, pa, kk, t);
            load_af(a[1], Ap, mb + 16 + g, pa, kk, t);
            #pragma unroll
            for (int j = 0; j < 2; ++j) {
                uint4 bf = B[(nw * 2 + j) * 32 + lane];
                mma16(acc2[0][2 * j],     a[0], bf.x, bf.y);
                mma16(acc2[1][2 * j],     a[1], bf.x, bf.y);
                mma16(acc2[0][2 * j + 1], a[0], bf.z, bf.w);
                mma16(acc2[1][2 * j + 1], a[1], bf.z, bf.w);
            }
            __syncthreads();
        }
    }

    // store O (fp32)
    {
        const int nb = nw * 32;
        #pragma unroll
        for (int mi = 0; mi < 2; ++mi) {
            int r0 = mb + mi * 16 + g;
            #pragma unroll
            for (int ni = 0; ni < 4; ++ni) {
                int c0 = nb + ni * 8 + 2 * t;
                *(float2*)(O + (size_t)r0 * P_O + c0)       = make_float2(acc2[mi][ni][0], acc2[mi][ni][1]);
                *(float2*)(O + (size_t)(r0 + 8) * P_O + c0) = make_float2(acc2[mi][ni][2], acc2[mi][ni][3]);
            }
        }
    }
    __syncthreads();

    // ---- epilogue: bias + LayerNorm + write + scatter ----
    int c4 = lane * 4;
    float4 g4 = *(const float4*)&ge[c4];
    float4 q4 = *(const float4*)&bge[c4];
    float bo0 = be2[c4 + 0] + ber[c4 + 0];
    float bo1 = be2[c4 + 1] + ber[c4 + 1];
    float bo2 = be2[c4 + 2] + ber[c4 + 2];
    float bo3 = be2[c4 + 3] + ber[c4 + 3];

    #pragma unroll
    for (int i = 0; i < 8; ++i) {
        int m = warp * 8 + i;
        const float* row = O + (size_t)m * P_O;
        float v0 = row[c4 + 0] + bo0, v1 = row[c4 + 1] + bo1;
        float v2 = row[c4 + 2] + bo2, v3 = row[c4 + 3] + bo3;
        float s = v0 + v1 + v2 + v3;
        float sq = v0 * v0 + v1 * v1 + v2 * v2 + v3 * v3;
        #pragma unroll
        for (int o = 16; o > 0; o >>= 1) {
            s  += __shfl_xor_sync(0xffffffffu, s, o);
            sq += __shfl_xor_sync(0xffffffffu, sq, o);
        }
        float mu = s * (1.f / 128.f);
        float var = sq * (1.f / 128.f) - mu * mu;
        float rstd = rsqrtf(var + 1e-5f);
        int e = e0 + m;
        if (e < E) {
            float4 y;
            y.x = (v0 - mu) * rstd * g4.x + q4.x;
            y.y = (v1 - mu) * rstd * g4.y + q4.y;
            y.z = (v2 - mu) * rstd * g4.z + q4.z;
            y.w = (v3 - mu) * rstd * g4.w + q4.w;
            *(float4*)&edge_out[(size_t)e * 128 + c4] = y;
            long long d = clampi(ldidx(ei, (long long)E + e, is64), Nn);
            float* ap = g_agg + (size_t)d * 128 + c4;
            atomicAdd(ap + 0, y.x);
            atomicAdd(ap + 1, y.y);
            atomicAdd(ap + 2, y.z);
            atomicAdd(ap + 3, y.w);
        }
    }
}

// ---------------------------------------------------------------------------
// Node kernel: 64 nodes/CTA, 2 CTAs/SM
// ---------------------------------------------------------------------------
__global__ void __launch_bounds__(THREADS, 2)
node_kernel(const float* __restrict__ x,
            const float* __restrict__ bn1, const float* __restrict__ bn2,
            const float* __restrict__ bnr,
            const float* __restrict__ gn,  const float* __restrict__ bgn,
            float* __restrict__ node_out, int Nn)
{
    extern __shared__ char smem[];
    __half* Ah = (__half*)(smem + N_A);
    __half* Hh = (__half*)(smem + N_H);
    float*  O  = (float*)(smem + N_H);
    char*   Bs = smem + N_B;

    const int tid  = threadIdx.x;
    const int warp = tid >> 5;
    const int lane = tid & 31;
    const int g    = lane >> 2;
    const int t    = lane & 3;
    const int n0   = blockIdx.x * TILE_M;

    #pragma unroll
    for (int sweep = 0; sweep < 8; ++sweep) {
        int m = sweep * 8 + warp;
        long long nn = min(n0 + m, Nn - 1);
        int k = lane * 4;
        float4 v0 = *(const float4*)(x + nn * 128 + k);
        float4 v1 = *(const float4*)(g_agg + nn * 128 + k);
        __half* row = Ah + (size_t)m * P_AN;
        st_perm4(row, k, v0);
        st_perm4(row, 128 + k, v1);
    }
    __syncthreads();

    const int mw = warp & 1;
    const int nw = warp >> 1;
    const int mb = mw * 32;

    // GEMM1: D1 = NH @ Wn1^T (64x256, K=256, 16 chunks)
    {
        float acc[2][8][4];
        #pragma unroll
        for (int mi = 0; mi < 2; ++mi)
            #pragma unroll
            for (int ni = 0; ni < 8; ++ni)
                #pragma unroll
                for (int q = 0; q < 4; ++q) acc[mi][ni][q] = 0.f;

        copy_w<4096>(Bs, g_wtf + OFF_Wn1, 0, tid);
        cpa_commit();
        for (int c = 0; c < 16; ++c) {
            if (c + 1 < 16) {
                copy_w<4096>(Bs + ((c + 1) & 1) * BUFB, g_wtf + OFF_Wn1, c + 1, tid);
                cpa_commit();
                cpa_wait1();
            } else {
                cpa_wait0();
            }
            __syncthreads();
            const uint4* B = (const uint4*)(Bs + (c & 1) * BUFB);
            unsigned a[2][4];
            load_af(a[0], Ah, mb + g, P_AN, c * 16, t);
            load_af(a[1], Ah, mb + 16 + g, P_AN, c * 16, t);
            #pragma unroll
            for (int j = 0; j < 4; ++j) {
                uint4 bf = B[(nw * 4 + j) * 32 + lane];
                mma16(acc[0][2 * j],     a[0], bf.x, bf.y);
                mma16(acc[1][2 * j],     a[1], bf.x, bf.y);
                mma16(acc[0][2 * j + 1], a[0], bf.z, bf.w);
                mma16(acc[1][2 * j + 1], a[1], bf.z, bf.w);
            }
            __syncthreads();
        }

        const int nb = nw * 64;
        #pragma unroll
        for (int mi = 0; mi < 2; ++mi) {
            int r0 = mb + mi * 16 + g;
            #pragma unroll
            for (int ni = 0; ni < 8; ++ni) {
                int c0 = nb + ni * 8 + 2 * t;
                float b0 = __ldg(&bn1[c0]), b1 = __ldg(&bn1[c0 + 1]);
                float s0 = acc[mi][ni][0] + b0, s1 = acc[mi][ni][1] + b1;
                float s2 = acc[mi][ni][2] + b0, s3 = acc[mi][ni][3] + b1;
                s0 = s0 / (1.f + __expf(-s0));
                s1 = s1 / (1.f + __expf(-s1));
                s2 = s2 / (1.f + __expf(-s2));
                s3 = s3 / (1.f + __expf(-s3));
                int base = (nb + ni * 8) & ~15;
                int pp = 4 * t + 2 * (ni & 1);
                *(__half2*)(Hh + (size_t)r0 * P_H + base + pp)       = __floats2half2_rn(s0, s1);
                *(__half2*)(Hh + (size_t)(r0 + 8) * P_H + base + pp) = __floats2half2_rn(s2, s3);
            }
        }
        __syncthreads();
    }

    // GEMM2: O = H @ Wn2^T (16) + NH @ Wnr^T (16 chunks)
    float acc2[2][4][4];
    #pragma unroll
    for (int mi = 0; mi < 2; ++mi)
        #pragma unroll
        for (int ni = 0; ni < 4; ++ni)
            #pragma unroll
            for (int q = 0; q < 4; ++q) acc2[mi][ni][q] = 0.f;
    {
        const int NC = 32;
        copy_w<2048>(Bs, g_wtf + OFF_Wn2, 0, tid);
        cpa_commit();
        for (int c = 0; c < NC; ++c) {
            if (c + 1 < NC) {
                const __half* wsrc = (c + 1 < 16) ? (g_wtf + OFF_Wn2) : (g_wtf + OFF_Wnr);
                int cn = (c + 1 < 16) ? (c + 1) : (c + 1 - 16);
                copy_w<2048>(Bs + ((c + 1) & 1) * BUFB, wsrc, cn, tid);
                cpa_commit();
                cpa_wait1();
            } else {
                cpa_wait0();
            }
            __syncthreads();
            const uint4* B = (const uint4*)(Bs + (c & 1) * BUFB);
            const __half* Ap = (c < 16) ? Hh : Ah;
            const int pa     = (c < 16) ? P_H : P_AN;
            const int kk     = ((c < 16) ? c : (c - 16)) * 16;
            unsigned a[2][4];
            load_af(a[0], Ap, mb + g, pa, kk, t);
            load_af(a[1], Ap, mb + 16 + g, pa, kk, t);
            #pragma unroll
            for (int j = 0; j < 2; ++j) {
                uint4 bf = B[(nw * 2 + j) * 32 + lane];
                mma16(acc2[0][2 * j],     a[0], bf.x, bf.y);
                mma16(acc2[1][2 * j],     a[1], bf.x, bf.y);
                mma16(acc2[0][2 * j + 1], a[0], bf.z, bf.w);
                mma16(acc2[1][2 * j + 1], a[1], bf.z, bf.w);
            }
            __syncthreads();
        }
    }

    {
        const int nb = nw * 32;
        #pragma unroll
        for (int mi = 0; mi < 2; ++mi) {
            int r0 = mb + mi * 16 + g;
            #pragma unroll
            for (int ni = 0; ni < 4; ++ni) {
                int c0 = nb + ni * 8 + 2 * t;
                *(float2*)(O + (size_t)r0 * P_O + c0)       = make_float2(acc2[mi][ni][0], acc2[mi][ni][1]);
                *(float2*)(O + (size_t)(r0 + 8) * P_O + c0) = make_float2(acc2[mi][ni][2], acc2[mi][ni][3]);
            }
        }
    }
    __syncthreads();

    int c4 = lane * 4;
    float4 g4 = *(const float4*)&gn[c4];
    float4 q4 = *(const float4*)&bgn[c4];
    float bo0 = bn2[c4 + 0] + bnr[c4 + 0];
    float bo1 = bn2[c4 + 1] + bnr[c4 + 1];
    float bo2 = bn2[c4 + 2] + bnr[c4 + 2];
    float bo3 = bn2[c4 + 3] + bnr[c4 + 3];

    #pragma unroll
    for (int i = 0; i < 8; ++i) {
        int m = warp * 8 + i;
        const float* row = O + (size_t)m * P_O;
        float v0 = row[c4 + 0] + bo0, v1 = row[c4 + 1] + bo1;
        float v2 = row[c4 + 2] + bo2, v3 = row[c4 + 3] + bo3;
        float s = v0 + v1 + v2 + v3;
        float sq = v0 * v0 + v1 * v1 + v2 * v2 + v3 * v3;
        #pragma unroll
        for (int o = 16; o > 0; o >>= 1) {
            s  += __shfl_xor_sync(0xffffffffu, s, o);
            sq += __shfl_xor_sync(0xffffffffu, sq, o);
        }
        float mu = s * (1.f / 128.f);
        float var = sq * (1.f / 128.f) - mu * mu;
        float rstd = rsqrtf(var + 1e-5f);
        int n = n0 + m;
        if (n < Nn) {
            float4 y;
            y.x = (v0 - mu) * rstd * g4.x + q4.x;
            y.y = (v1 - mu) * rstd * g4.y + q4.y;
            y.z = (v2 - mu) * rstd * g4.z + q4.z;
            y.w = (v3 - mu) * rstd * g4.w + q4.w;
            *(float4*)&node_out[(size_t)n * 128 + c4] = y;
        }
    }
}

extern "C" void kernel_launch(void* const* d_in, const int* in_sizes, int n_in,
                              void* d_out, int out_size) {
    const float* x   = (const float*)d_in[0];
    const float* ea  = (const float*)d_in[1];
    const void*  ei  = d_in[2];
    const float* We1 = (const float*)d_in[3];
    const float* be1 = (const float*)d_in[4];
    const float* We2 = (const float*)d_in[5];
    const float* be2 = (const float*)d_in[6];
    const float* Wer = (const float*)d_in[7];
    const float* ber = (const float*)d_in[8];
    const float* ge  = (const float*)d_in[9];
    const float* bge = (const float*)d_in[10];
    const float* Wn1 = (const float*)d_in[11];
    const float* bn1 = (const float*)d_in[12];
    const float* Wn2 = (const float*)d_in[13];
    const float* bn2 = (const float*)d_in[14];
    const float* Wnr = (const float*)d_in[15];
    const float* bnr = (const float*)d_in[16];
    const float* gn  = (const float*)d_in[17];
    const float* bgn = (const float*)d_in[18];

    int Nn = in_sizes[0] / 128;
    int E  = in_sizes[1] / 128;

    float* out      = (float*)d_out;
    float* node_out = out;
    float* edge_out = out + (size_t)Nn * 128;

    cudaFuncSetAttribute(edge_kernel, cudaFuncAttributeMaxDynamicSharedMemorySize, E_TOTAL);
    cudaFuncSetAttribute(node_kernel, cudaFuncAttributeMaxDynamicSharedMemorySize, N_TOTAL);

    probe_idx_kernel<<<1, 64>>>(ei, E, Nn);
    cvt_weights_kernel<<<(W_TOTAL + 255) / 256, 256>>>(We1, We2, Wer, Wn1, Wn2, Wnr);

    int nf4 = Nn * 32;
    zero_agg_kernel<<<(nf4 + 255) / 256, 256>>>(nf4);

    edge_kernel<<<(E + TILE_M - 1) / TILE_M, THREADS, E_TOTAL>>>(
        x, ea, ei, be1, be2, ber, ge, bge, edge_out, E, Nn);

    node_kernel<<<(Nn + TILE_M - 1) / TILE_M, THREADS, N_TOTAL>>>(
        x, bn1, bn2, bnr, gn, bgn, node_out, Nn);
}

// round 17
// speedup vs baseline: 2.5880x; 1.1016x over previous
#include <cuda_runtime.h>
#include <cuda_fp16.h>

// GraphNetBlock — fp16 mma.sync.m16n8k16, v2: 3-stage weight pipeline with ONE
// barrier per chunk; GEMM2 processes 2 packed chunks per iteration.
// cvt_weights + probe + zero_agg -> edge_kernel -> node_kernel
// out layout: node_out [N,128] then edge_out [E,128].

#define THREADS 256
#define TILE_M 64

#define P_A  400   // A pitch in halves (K=384+pad); 200 words == 8 mod 32
#define P_AN 272   // node A pitch (K=256+pad)
#define P_H  272   // H pitch (halves)
#define P_O  132   // O pitch (floats)

// smem maps (bytes)
#define E_A 0
#define E_H 51200            // 64*400*2
#define E_B 86016            // E_H + 64*272*2
#define E_TOTAL 110592       // E_B + 3*8192
#define N_A 0
#define N_H 34816            // 64*272*2
#define N_B 69632
#define N_TOTAL 94208        // N_B + 3*8192
#define BUFB 8192            // weight chunk buffer stride (bytes)

__device__ float g_agg[65536 * 128];
__device__ int g_is64;

// f16 weights, fragment-interleaved for m16n8k16 (16-k chunks)
#define OFF_We1 0
#define OFF_We2 98304
#define OFF_Wer 131072
#define OFF_Wn1 180224
#define OFF_Wn2 245760
#define OFF_Wnr 278528
#define W_TOTAL 311296
__device__ __half g_wtf[W_TOTAL];

// ---------------- helpers ----------------
__device__ __forceinline__ void mma16(float c[4], const unsigned a[4], unsigned b0, unsigned b1) {
    asm volatile(
        "mma.sync.aligned.m16n8k16.row.col.f32.f16.f16.f32 "
        "{%0,%1,%2,%3}, {%4,%5,%6,%7}, {%8,%9}, {%0,%1,%2,%3};"
        : "+f"(c[0]), "+f"(c[1]), "+f"(c[2]), "+f"(c[3])
        : "r"(a[0]), "r"(a[1]), "r"(a[2]), "r"(a[3]), "r"(b0), "r"(b1));
}

// A fragment (m16k16) from k-permuted f16 tile: 2 x LDS.64
__device__ __forceinline__ void load_af(unsigned a[4], const __half* Ap, int rowg,
                                        int pa, int kk, int t) {
    const __half* p = Ap + (size_t)rowg * pa + kk + t * 4;
    uint2 lo = *(const uint2*)p;
    uint2 hi = *(const uint2*)(p + 8 * pa);
    a[0] = lo.x; a[1] = hi.x; a[2] = lo.y; a[3] = hi.y;
}

// store 4 fp32 as f16 at (row, k0..k0+3) with k16-block permutation
__device__ __forceinline__ void st_perm4(__half* row, int k0, float4 v) {
    int kb = k0 & ~15;
    int v0 = k0 & 15;
    int p0 = ((v0 >> 1) & 3) * 4 + ((v0 >> 3) << 1);
    int v2 = v0 + 2;
    int p2 = ((v2 >> 1) & 3) * 4 + ((v2 >> 3) << 1);
    *(__half2*)(row + kb + p0) = __floats2half2_rn(v.x, v.y);
    *(__half2*)(row + kb + p2) = __floats2half2_rn(v.z, v.w);
}

__device__ __forceinline__ void cpa16(char* dst, const char* src) {
    unsigned d = (unsigned)__cvta_generic_to_shared(dst);
    asm volatile("cp.async.cg.shared.global [%0], [%1], 16;" :: "r"(d), "l"(src));
}
__device__ __forceinline__ void cpa_commit() { asm volatile("cp.async.commit_group;"); }
__device__ __forceinline__ void cpa_wait1() { asm volatile("cp.async.wait_group 1;"); }
__device__ __forceinline__ void cpa_wait0() { asm volatile("cp.async.wait_group 0;"); }

// copy one frag-layout weight chunk (NHALVES halves, contiguous) gmem -> smem
template<int NHALVES>
__device__ __forceinline__ void copy_w(char* dst, const __half* wbase, int chunk, int tid) {
    const char* src = (const char*)(wbase + (size_t)chunk * NHALVES);
    #pragma unroll
    for (int i = tid * 16; i < NHALVES * 2; i += THREADS * 16) cpa16(dst + i, src + i);
}

__device__ __forceinline__ long long ldidx(const void* ei, long long i, int is64) {
    if (is64) return ((const long long*)ei)[i];
    return (long long)((const int*)ei)[i];
}
__device__ __forceinline__ long long clampi(long long v, int Nn) {
    if (v < 0) return 0;
    if (v >= Nn) return Nn - 1;
    return v;
}

__global__ void probe_idx_kernel(const void* ei, int E, int Nn) {
    int n = E < 64 ? E : 64;
    int bad = 0;
    if (threadIdx.x < n) {
        long long v = ((const long long*)ei)[threadIdx.x];
        bad = (v < 0 || v >= Nn);
    }
    unsigned ab = __ballot_sync(0xffffffffu, bad);
    __shared__ unsigned s[2];
    if ((threadIdx.x & 31) == 0) s[threadIdx.x >> 5] = ab;
    __syncthreads();
    if (threadIdx.x == 0) g_is64 = (s[0] | s[1]) ? 0 : 1;
}

__global__ void zero_agg_kernel(int nf4) {
    int i = blockIdx.x * blockDim.x + threadIdx.x;
    if (i < nf4) ((float4*)g_agg)[i] = make_float4(0.f, 0.f, 0.f, 0.f);
}

// fp32 W[K][N] -> f16 fragment-interleaved, 16-k chunks.
__global__ void cvt_weights_kernel(const float* We1, const float* We2, const float* Wer,
                                   const float* Wn1, const float* Wn2, const float* Wnr) {
    int i = blockIdx.x * blockDim.x + threadIdx.x;
    if (i >= W_TOTAL) return;
    const float* src; int off; int N;
    if      (i < OFF_We2) { src = We1; off = OFF_We1; N = 256; }
    else if (i < OFF_Wer) { src = We2; off = OFF_We2; N = 128; }
    else if (i < OFF_Wn1) { src = Wer; off = OFF_Wer; N = 128; }
    else if (i < OFF_Wn2) { src = Wn1; off = OFF_Wn1; N = 256; }
    else if (i < OFF_Wnr) { src = Wn2; off = OFF_Wn2; N = 128; }
    else                  { src = Wnr; off = OFF_Wnr; N = 128; }
    int lf = i - off;
    int k = lf / N, n = lf % N;
    int kt = k >> 4, kk = k & 15;
    int lane = (n & 7) * 4 + ((kk & 7) >> 1);
    int h = ((kk >> 3) << 1) | (kk & 1);
    int T = n >> 3;
    int dest = off + kt * N * 16 + ((T >> 1) * 32 + lane) * 8 + (T & 1) * 4 + h;
    g_wtf[dest] = __float2half_rn(src[lf]);
}

// ---------------------------------------------------------------------------
// Edge kernel: 64 edges/CTA, 2 CTAs/SM
// ---------------------------------------------------------------------------
__global__ void __launch_bounds__(THREADS, 2)
edge_kernel(const float* __restrict__ x, const float* __restrict__ ea,
            const void* __restrict__ ei,
            const float* __restrict__ be1, const float* __restrict__ be2,
            const float* __restrict__ ber,
            const float* __restrict__ ge,  const float* __restrict__ bge,
            float* __restrict__ edge_out, int E, int Nn)
{
    extern __shared__ char smem[];
    __half* Ah = (__half*)(smem + E_A);
    __half* Hh = (__half*)(smem + E_H);
    float*  O  = (float*)(smem + E_H);
    char*   Bs = smem + E_B;

    const int tid  = threadIdx.x;
    const int warp = tid >> 5;
    const int lane = tid & 31;
    const int g    = lane >> 2;
    const int t    = lane & 3;
    const int e0   = blockIdx.x * TILE_M;
    const int is64 = g_is64;

    // prologue copies for GEMM1 overlap the gather
    copy_w<4096>(Bs,        g_wtf + OFF_We1, 0, tid); cpa_commit();
    copy_w<4096>(Bs + BUFB, g_wtf + OFF_We1, 1, tid); cpa_commit();

    // gather EH = [ea | x[src] | x[dst]] (f16, k-permuted)
    #pragma unroll
    for (int sweep = 0; sweep < 8; ++sweep) {
        int m = sweep * 8 + warp;
        long long ecl = min(e0 + m, E - 1);
        long long s = clampi(ldidx(ei, ecl, is64), Nn);
        long long d = clampi(ldidx(ei, (long long)E + ecl, is64), Nn);
        int k = lane * 4;
        float4 v0 = *(const float4*)(ea + ecl * 128 + k);
        float4 v1 = *(const float4*)(x + s * 128 + k);
        float4 v2 = *(const float4*)(x + d * 128 + k);
        __half* row = Ah + (size_t)m * P_A;
        st_perm4(row, k, v0);
        st_perm4(row, 128 + k, v1);
        st_perm4(row, 256 + k, v2);
    }

    const int mw = warp & 1;         // 2 x m32
    const int nw = warp >> 1;        // 4 x n64 (GEMM1) / n32 (GEMM2)
    const int mb = mw * 32;

    // ============ GEMM1: D1 = EH @ We1^T (64x256, K=384, 24 chunks, 3-stage) ============
    float acc[2][8][4];
    #pragma unroll
    for (int mi = 0; mi < 2; ++mi)
        #pragma unroll
        for (int ni = 0; ni < 8; ++ni)
            #pragma unroll
            for (int q = 0; q < 4; ++q) acc[mi][ni][q] = 0.f;

    for (int c = 0; c < 24; ++c) {
        if (c + 1 < 24) cpa_wait1(); else cpa_wait0();
        __syncthreads();
        if (c + 2 < 24) {
            copy_w<4096>(Bs + ((c + 2) % 3) * BUFB, g_wtf + OFF_We1, c + 2, tid);
            cpa_commit();
        }
        const uint4* B = (const uint4*)(Bs + (c % 3) * BUFB);
        unsigned a[2][4];
        load_af(a[0], Ah, mb + g, P_A, c * 16, t);
        load_af(a[1], Ah, mb + 16 + g, P_A, c * 16, t);
        #pragma unroll
        for (int j = 0; j < 4; ++j) {
            uint4 bf = B[(nw * 4 + j) * 32 + lane];
            mma16(acc[0][2 * j],     a[0], bf.x, bf.y);
            mma16(acc[1][2 * j],     a[1], bf.x, bf.y);
            mma16(acc[0][2 * j + 1], a[0], bf.z, bf.w);
            mma16(acc[1][2 * j + 1], a[1], bf.z, bf.w);
        }
    }
    __syncthreads();   // all warps done reading last GEMM1 buffer

    // GEMM2 prologue copies (iters 0,1 -> buf0,buf1), overlap SiLU epilogue
    copy_w<2048>(Bs,          g_wtf + OFF_We2, 0, tid);
    copy_w<2048>(Bs + 4096,   g_wtf + OFF_We2, 1, tid); cpa_commit();
    copy_w<2048>(Bs + BUFB,        g_wtf + OFF_We2, 2, tid);
    copy_w<2048>(Bs + BUFB + 4096, g_wtf + OFF_We2, 3, tid); cpa_commit();

    // SiLU + bias -> H (f16, k-permuted)
    {
        const int nb = nw * 64;
        #pragma unroll
        for (int mi = 0; mi < 2; ++mi) {
            int r0 = mb + mi * 16 + g;
            #pragma unroll
            for (int ni = 0; ni < 8; ++ni) {
                int c0 = nb + ni * 8 + 2 * t;
                float b0 = __ldg(&be1[c0]), b1 = __ldg(&be1[c0 + 1]);
                float s0 = acc[mi][ni][0] + b0, s1 = acc[mi][ni][1] + b1;
                float s2 = acc[mi][ni][2] + b0, s3 = acc[mi][ni][3] + b1;
                s0 = s0 / (1.f + __expf(-s0));
                s1 = s1 / (1.f + __expf(-s1));
                s2 = s2 / (1.f + __expf(-s2));
                s3 = s3 / (1.f + __expf(-s3));
                int base = (nb + ni * 8) & ~15;
                int pp = 4 * t + 2 * (ni & 1);
                *(__half2*)(Hh + (size_t)r0 * P_H + base + pp)       = __floats2half2_rn(s0, s1);
                *(__half2*)(Hh + (size_t)(r0 + 8) * P_H + base + pp) = __floats2half2_rn(s2, s3);
            }
        }
    }

    // ============ GEMM2: O = H @ We2^T (16) + EH @ Wer^T (24 chunks), 20 iters x2 ============
    float acc2[2][4][4];
    #pragma unroll
    for (int mi = 0; mi < 2; ++mi)
        #pragma unroll
        for (int ni = 0; ni < 4; ++ni)
            #pragma unroll
            for (int q = 0; q < 4; ++q) acc2[mi][ni][q] = 0.f;
    {
        const int NI = 20;
        for (int i = 0; i < NI; ++i) {
            if (i + 1 < NI) cpa_wait1(); else cpa_wait0();
            __syncthreads();
            if (i + 2 < NI) {
                char* db = Bs + ((i + 2) % 3) * BUFB;
                int c0 = 2 * (i + 2), c1 = c0 + 1;
                const __half* w0 = (c0 < 16) ? (g_wtf + OFF_We2) : (g_wtf + OFF_Wer);
                const __half* w1 = (c1 < 16) ? (g_wtf + OFF_We2) : (g_wtf + OFF_Wer);
                copy_w<2048>(db,        w0, (c0 < 16) ? c0 : c0 - 16, tid);
                copy_w<2048>(db + 4096, w1, (c1 < 16) ? c1 : c1 - 16, tid);
                cpa_commit();
            }
            const char* Bb = Bs + (i % 3) * BUFB;
            #pragma unroll
            for (int s = 0; s < 2; ++s) {
                int c = 2 * i + s;
                const uint4* B = (const uint4*)(Bb + s * 4096);
                const __half* Ap = (c < 16) ? Hh : Ah;
                const int pa     = (c < 16) ? P_H : P_A;
                const int kk     = ((c < 16) ? c : (c - 16)) * 16;
                unsigned a[2][4];
                load_af(a[0], Ap, mb + g, pa, kk, t);
                load_af(a[1], Ap, mb + 16 + g, pa, kk, t);
                #pragma unroll
                for (int j = 0; j < 2; ++j) {
                    uint4 bf = B[(nw * 2 + j) * 32 + lane];
                    mma16(acc2[0][2 * j],     a[0], bf.x, bf.y);
                    mma16(acc2[1][2 * j],     a[1], bf.x, bf.y);
                    mma16(acc2[0][2 * j + 1], a[0], bf.z, bf.w);
                    mma16(acc2[1][2 * j + 1], a[1], bf.z, bf.w);
                }
            }
        }
    }

    // store O (fp32) — per-warp own region; no cross-warp hazard before sync
    {
        const int nb = nw * 32;
        #pragma unroll
        for (int mi = 0; mi < 2; ++mi) {
            int r0 = mb + mi * 16 + g;
            #pragma unroll
            for (int ni = 0; ni < 4; ++ni) {
                int c0 = nb + ni * 8 + 2 * t;
                *(float2*)(O + (size_t)r0 * P_O + c0)       = make_float2(acc2[mi][ni][0], acc2[mi][ni][1]);
                *(float2*)(O + (size_t)(r0 + 8) * P_O + c0) = make_float2(acc2[mi][ni][2], acc2[mi][ni][3]);
            }
        }
    }
    __syncthreads();

    // ---- epilogue: bias + LayerNorm + write + scatter ----
    int c4 = lane * 4;
    float4 g4 = *(const float4*)&ge[c4];
    float4 q4 = *(const float4*)&bge[c4];
    float bo0 = be2[c4 + 0] + ber[c4 + 0];
    float bo1 = be2[c4 + 1] + ber[c4 + 1];
    float bo2 = be2[c4 + 2] + ber[c4 + 2];
    float bo3 = be2[c4 + 3] + ber[c4 + 3];

    #pragma unroll
    for (int i = 0; i < 8; ++i) {
        int m = warp * 8 + i;
        const float* row = O + (size_t)m * P_O;
        float v0 = row[c4 + 0] + bo0, v1 = row[c4 + 1] + bo1;
        float v2 = row[c4 + 2] + bo2, v3 = row[c4 + 3] + bo3;
        float s = v0 + v1 + v2 + v3;
        float sq = v0 * v0 + v1 * v1 + v2 * v2 + v3 * v3;
        #pragma unroll
        for (int o = 16; o > 0; o >>= 1) {
            s  += __shfl_xor_sync(0xffffffffu, s, o);
            sq += __shfl_xor_sync(0xffffffffu, sq, o);
        }
        float mu = s * (1.f / 128.f);
        float var = sq * (1.f / 128.f) - mu * mu;
        float rstd = rsqrtf(var + 1e-5f);
        int e = e0 + m;
        if (e < E) {
            float4 y;
            y.x = (v0 - mu) * rstd * g4.x + q4.x;
            y.y = (v1 - mu) * rstd * g4.y + q4.y;
            y.z = (v2 - mu) * rstd * g4.z + q4.z;
            y.w = (v3 - mu) * rstd * g4.w + q4.w;
            *(float4*)&edge_out[(size_t)e * 128 + c4] = y;
            long long d = clampi(ldidx(ei, (long long)E + e, is64), Nn);
            float* ap = g_agg + (size_t)d * 128 + c4;
            atomicAdd(ap + 0, y.x);
            atomicAdd(ap + 1, y.y);
            atomicAdd(ap + 2, y.z);
            atomicAdd(ap + 3, y.w);
        }
    }
}

// ---------------------------------------------------------------------------
// Node kernel: 64 nodes/CTA, 2 CTAs/SM
// ---------------------------------------------------------------------------
__global__ void __launch_bounds__(THREADS, 2)
node_kernel(const float* __restrict__ x,
            const float* __restrict__ bn1, const float* __restrict__ bn2,
            const float* __restrict__ bnr,
            const float* __restrict__ gn,  const float* __restrict__ bgn,
            float* __restrict__ node_out, int Nn)
{
    extern __shared__ char smem[];
    __half* Ah = (__half*)(smem + N_A);
    __half* Hh = (__half*)(smem + N_H);
    float*  O  = (float*)(smem + N_H);
    char*   Bs = smem + N_B;

    const int tid  = threadIdx.x;
    const int warp = tid >> 5;
    const int lane = tid & 31;
    const int g    = lane >> 2;
    const int t    = lane & 3;
    const int n0   = blockIdx.x * TILE_M;

    copy_w<4096>(Bs,        g_wtf + OFF_Wn1, 0, tid); cpa_commit();
    copy_w<4096>(Bs + BUFB, g_wtf + OFF_Wn1, 1, tid); cpa_commit();

    #pragma unroll
    for (int sweep = 0; sweep < 8; ++sweep) {
        int m = sweep * 8 + warp;
        long long nn = min(n0 + m, Nn - 1);
        int k = lane * 4;
        float4 v0 = *(const float4*)(x + nn * 128 + k);
        float4 v1 = *(const float4*)(g_agg + nn * 128 + k);
        __half* row = Ah + (size_t)m * P_AN;
        st_perm4(row, k, v0);
        st_perm4(row, 128 + k, v1);
    }

    const int mw = warp & 1;
    const int nw = warp >> 1;
    const int mb = mw * 32;

    // GEMM1: D1 = NH @ Wn1^T (64x256, K=256, 16 chunks, 3-stage)
    float acc[2][8][4];
    #pragma unroll
    for (int mi = 0; mi < 2; ++mi)
        #pragma unroll
        for (int ni = 0; ni < 8; ++ni)
            #pragma unroll
            for (int q = 0; q < 4; ++q) acc[mi][ni][q] = 0.f;

    for (int c = 0; c < 16; ++c) {
        if (c + 1 < 16) cpa_wait1(); else cpa_wait0();
        __syncthreads();
        if (c + 2 < 16) {
            copy_w<4096>(Bs + ((c + 2) % 3) * BUFB, g_wtf + OFF_Wn1, c + 2, tid);
            cpa_commit();
        }
        const uint4* B = (const uint4*)(Bs + (c % 3) * BUFB);
        unsigned a[2][4];
        load_af(a[0], Ah, mb + g, P_AN, c * 16, t);
        load_af(a[1], Ah, mb + 16 + g, P_AN, c * 16, t);
        #pragma unroll
        for (int j = 0; j < 4; ++j) {
            uint4 bf = B[(nw * 4 + j) * 32 + lane];
            mma16(acc[0][2 * j],     a[0], bf.x, bf.y);
            mma16(acc[1][2 * j],     a[1], bf.x, bf.y);
            mma16(acc[0][2 * j + 1], a[0], bf.z, bf.w);
            mma16(acc[1][2 * j + 1], a[1], bf.z, bf.w);
        }
    }
    __syncthreads();

    copy_w<2048>(Bs,          g_wtf + OFF_Wn2, 0, tid);
    copy_w<2048>(Bs + 4096,   g_wtf + OFF_Wn2, 1, tid); cpa_commit();
    copy_w<2048>(Bs + BUFB,        g_wtf + OFF_Wn2, 2, tid);
    copy_w<2048>(Bs + BUFB + 4096, g_wtf + OFF_Wn2, 3, tid); cpa_commit();

    {
        const int nb = nw * 64;
        #pragma unroll
        for (int mi = 0; mi < 2; ++mi) {
            int r0 = mb + mi * 16 + g;
            #pragma unroll
            for (int ni = 0; ni < 8; ++ni) {
                int c0 = nb + ni * 8 + 2 * t;
                float b0 = __ldg(&bn1[c0]), b1 = __ldg(&bn1[c0 + 1]);
                float s0 = acc[mi][ni][0] + b0, s1 = acc[mi][ni][1] + b1;
                float s2 = acc[mi][ni][2] + b0, s3 = acc[mi][ni][3] + b1;
                s0 = s0 / (1.f + __expf(-s0));
                s1 = s1 / (1.f + __expf(-s1));
                s2 = s2 / (1.f + __expf(-s2));
                s3 = s3 / (1.f + __expf(-s3));
                int base = (nb + ni * 8) & ~15;
                int pp = 4 * t + 2 * (ni & 1);
                *(__half2*)(Hh + (size_t)r0 * P_H + base + pp)       = __floats2half2_rn(s0, s1);
                *(__half2*)(Hh + (size_t)(r0 + 8) * P_H + base + pp) = __floats2half2_rn(s2, s3);
            }
        }
    }

    // GEMM2: O = H @ Wn2^T (16) + NH @ Wnr^T (16 chunks), 16 iters x2
    float acc2[2][4][4];
    #pragma unroll
    for (int mi = 0; mi < 2; ++mi)
        #pragma unroll
        for (int ni = 0; ni < 4; ++ni)
            #pragma unroll
            for (int q = 0; q < 4; ++q) acc2[mi][ni][q] = 0.f;
    {
        const int NI = 16;
        for (int i = 0; i < NI; ++i) {
            if (i + 1 < NI) cpa_wait1(); else cpa_wait0();
            __syncthreads();
            if (i + 2 < NI) {
                char* db = Bs + ((i + 2) % 3) * BUFB;
                int c0 = 2 * (i + 2), c1 = c0 + 1;
                const __half* w0 = (c0 < 16) ? (g_wtf + OFF_Wn2) : (g_wtf + OFF_Wnr);
                const __half* w1 = (c1 < 16) ? (g_wtf + OFF_Wn2) : (g_wtf + OFF_Wnr);
                copy_w<2048>(db,        w0, (c0 < 16) ? c0 : c0 - 16, tid);
                copy_w<2048>(db + 4096, w1, (c1 < 16) ? c1 : c1 - 16, tid);
                cpa_commit();
            }
            const char* Bb = Bs + (i % 3) * BUFB;
            #pragma unroll
            for (int s = 0; s < 2; ++s) {
                int c = 2 * i + s;
                const uint4* B = (const uint4*)(Bb + s * 4096);
                const __half* Ap = (c < 16) ? Hh : Ah;
                const int pa     = (c < 16) ? P_H : P_AN;
                const int kk     = ((c < 16) ? c : (c - 16)) * 16;
                unsigned a[2][4];
                load_af(a[0], Ap, mb + g, pa, kk, t);
                load_af(a[1], Ap, mb + 16 + g, pa, kk, t);
                #pragma unroll
                for (int j = 0; j < 2; ++j) {
                    uint4 bf = B[(nw * 2 + j) * 32 + lane];
                    mma16(acc2[0][2 * j],     a[0], bf.x, bf.y);
                    mma16(acc2[1][2 * j],     a[1], bf.x, bf.y);
                    mma16(acc2[0][2 * j + 1], a[0], bf.z, bf.w);
                    mma16(acc2[1][2 * j + 1], a[1], bf.z, bf.w);
                }
            }
        }
    }

    {
        const int nb = nw * 32;
        #pragma unroll
        for (int mi = 0; mi < 2; ++mi) {
            int r0 = mb + mi * 16 + g;
            #pragma unroll
            for (int ni = 0; ni < 4; ++ni) {
                int c0 = nb + ni * 8 + 2 * t;
                *(float2*)(O + (size_t)r0 * P_O + c0)       = make_float2(acc2[mi][ni][0], acc2[mi][ni][1]);
                *(float2*)(O + (size_t)(r0 + 8) * P_O + c0) = make_float2(acc2[mi][ni][2], acc2[mi][ni][3]);
            }
        }
    }
    __syncthreads();

    int c4 = lane * 4;
    float4 g4 = *(const float4*)&gn[c4];
    float4 q4 = *(const float4*)&bgn[c4];
    float bo0 = bn2[c4 + 0] + bnr[c4 + 0];
    float bo1 = bn2[c4 + 1] + bnr[c4 + 1];
    float bo2 = bn2[c4 + 2] + bnr[c4 + 2];
    float bo3 = bn2[c4 + 3] + bnr[c4 + 3];

    #pragma unroll
    for (int i = 0; i < 8; ++i) {
        int m = warp * 8 + i;
        const float* row = O + (size_t)m * P_O;
        float v0 = row[c4 + 0] + bo0, v1 = row[c4 + 1] + bo1;
        float v2 = row[c4 + 2] + bo2, v3 = row[c4 + 3] + bo3;
        float s = v0 + v1 + v2 + v3;
        float sq = v0 * v0 + v1 * v1 + v2 * v2 + v3 * v3;
        #pragma unroll
        for (int o = 16; o > 0; o >>= 1) {
            s  += __shfl_xor_sync(0xffffffffu, s, o);
            sq += __shfl_xor_sync(0xffffffffu, sq, o);
        }
        float mu = s * (1.f / 128.f);
        float var = sq * (1.f / 128.f) - mu * mu;
        float rstd = rsqrtf(var + 1e-5f);
        int n = n0 + m;
        if (n < Nn) {
            float4 y;
            y.x = (v0 - mu) * rstd * g4.x + q4.x;
            y.y = (v1 - mu) * rstd * g4.y + q4.y;
            y.z = (v2 - mu) * rstd * g4.z + q4.z;
            y.w = (v3 - mu) * rstd * g4.w + q4.w;
            *(float4*)&node_out[(size_t)n * 128 + c4] = y;
        }
    }
}

extern "C" void kernel_launch(void* const* d_in, const int* in_sizes, int n_in,
                              void* d_out, int out_size) {
    const float* x   = (const float*)d_in[0];
    const float* ea  = (const float*)d_in[1];
    const void*  ei  = d_in[2];
    const float* We1 = (const float*)d_in[3];
    const float* be1 = (const float*)d_in[4];
    const float* We2 = (const float*)d_in[5];
    const float* be2 = (const float*)d_in[6];
    const float* Wer = (const float*)d_in[7];
    const float* ber = (const float*)d_in[8];
    const float* ge  = (const float*)d_in[9];
    const float* bge = (const float*)d_in[10];
    const float* Wn1 = (const float*)d_in[11];
    const float* bn1 = (const float*)d_in[12];
    const float* Wn2 = (const float*)d_in[13];
    const float* bn2 = (const float*)d_in[14];
    const float* Wnr = (const float*)d_in[15];
    const float* bnr = (const float*)d_in[16];
    const float* gn  = (const float*)d_in[17];
    const float* bgn = (const float*)d_in[18];

    int Nn = in_sizes[0] / 128;
    int E  = in_sizes[1] / 128;

    float* out      = (float*)d_out;
    float* node_out = out;
    float* edge_out = out + (size_t)Nn * 128;

    cudaFuncSetAttribute(edge_kernel, cudaFuncAttributeMaxDynamicSharedMemorySize, E_TOTAL);
    cudaFuncSetAttribute(node_kernel, cudaFuncAttributeMaxDynamicSharedMemorySize, N_TOTAL);

    probe_idx_kernel<<<1, 64>>>(ei, E, Nn);
    cvt_weights_kernel<<<(W_TOTAL + 255) / 256, 256>>>(We1, We2, Wer, Wn1, Wn2, Wnr);

    int nf4 = Nn * 32;
    zero_agg_kernel<<<(nf4 + 255) / 256, 256>>>(nf4);

    edge_kernel<<<(E + TILE_M - 1) / TILE_M, THREADS, E_TOTAL>>>(
        x, ea, ei, be1, be2, ber, ge, bge, edge_out, E, Nn);

    node_kernel<<<(Nn + TILE_M - 1) / TILE_M, THREADS, N_TOTAL>>>(
        x, bn1, bn2, bnr, gn, bgn, node_out, Nn);
}